// round 1
// baseline (speedup 1.0000x reference)
#include <cuda_runtime.h>
#include <cuda_bf16.h>
#include <cstdint>

// Problem constants (from reference): D_FEAT = 64 floats = 16 float4 chunks per row.
static constexpr int D4 = 16;   // float4 chunks per feature row

__global__ void zero_out_kernel(float4* __restrict__ out4, int n4) {
    int i = blockIdx.x * blockDim.x + threadIdx.x;
    if (i < n4) out4[i] = make_float4(0.f, 0.f, 0.f, 0.f);
}

// One edge handled by 16 consecutive threads; thread owns one float4 chunk.
// gather embeds[cols[e]] (coalesced 256B), scale by vals[e], vectorized
// atomic reduce into out[rows[e]] (RED.E.ADD.F32 x4 / 128-bit red).
__global__ void spmm_scatter_kernel(const int*   __restrict__ rows,
                                    const int*   __restrict__ cols,
                                    const float* __restrict__ vals,
                                    const float4* __restrict__ embeds4,
                                    float4* __restrict__ out4,
                                    int n_edges) {
    int gid = blockIdx.x * blockDim.x + threadIdx.x;
    int e = gid >> 4;          // edge index
    int c = gid & 15;          // chunk within feature row
    if (e >= n_edges) return;

    int   row = __ldg(rows + e);
    int   col = __ldg(cols + e);
    float v   = __ldg(vals + e);

    float4 x = __ldg(embeds4 + (size_t)col * D4 + c);
    x.x *= v; x.y *= v; x.z *= v; x.w *= v;

    atomicAdd(out4 + (size_t)row * D4 + c, x);   // sm_90+: 128-bit red.global.add.v4.f32
}

extern "C" void kernel_launch(void* const* d_in, const int* in_sizes, int n_in,
                              void* d_out, int out_size) {
    const int*   rows   = (const int*)  d_in[0];
    const int*   cols   = (const int*)  d_in[1];
    const float* vals   = (const float*)d_in[2];
    const float4* emb4  = (const float4*)d_in[3];
    float4* out4 = (float4*)d_out;

    int n_edges = in_sizes[0];
    int out_n4  = out_size / 4;   // out_size floats -> float4 count

    {
        int threads = 256;
        int blocks = (out_n4 + threads - 1) / threads;
        zero_out_kernel<<<blocks, threads>>>(out4, out_n4);
    }
    {
        long long total = (long long)n_edges * 16;
        int threads = 256;
        long long blocks = (total + threads - 1) / threads;
        spmm_scatter_kernel<<<(unsigned)blocks, threads>>>(rows, cols, vals, emb4, out4, n_edges);
    }
}

// round 4
// speedup vs baseline: 1.0932x; 1.0932x over previous
#include <cuda_runtime.h>
#include <cuda_bf16.h>
#include <cstdint>

// Problem constants (fixed by the reference): 100k nodes, 1.25M edges, D=64 floats.
#define N_NODES 100000
#define N_EDGES 1250000
#define D4      16            // float4 chunks per feature row

#define SCAN_T  1024
#define NB_SCAN ((N_NODES + SCAN_T - 1) / SCAN_T)   // 98

// Scratch (static device globals — allocation-free per harness rules)
__device__ int  g_counts[N_NODES];        // degrees, then scatter cursors
__device__ int  g_ptr[N_NODES + 1];       // CSR row pointers
__device__ int  g_blocktotals[128];       // scan partials (NB_SCAN <= 128)
__device__ int2 g_edges[N_EDGES];         // CSR-ordered {col, val_bits}

__global__ void k_zero_counts() {
    int i = blockIdx.x * blockDim.x + threadIdx.x;
    if (i < N_NODES) g_counts[i] = 0;
}

__global__ void k_hist(const int* __restrict__ rows) {
    int e = blockIdx.x * blockDim.x + threadIdx.x;
    if (e < N_EDGES) atomicAdd(&g_counts[rows[e]], 1);
}

// Block-local exclusive scan of counts -> g_ptr (local part) + block totals.
__global__ void k_scan_local() {
    __shared__ int sh[SCAN_T];
    int gid = blockIdx.x * SCAN_T + threadIdx.x;
    int v = (gid < N_NODES) ? g_counts[gid] : 0;
    sh[threadIdx.x] = v;
    __syncthreads();
    #pragma unroll
    for (int off = 1; off < SCAN_T; off <<= 1) {
        int t = (threadIdx.x >= off) ? sh[threadIdx.x - off] : 0;
        __syncthreads();
        sh[threadIdx.x] += t;
        __syncthreads();
    }
    if (gid < N_NODES) g_ptr[gid] = sh[threadIdx.x] - v;           // exclusive
    if (threadIdx.x == SCAN_T - 1) g_blocktotals[blockIdx.x] = sh[threadIdx.x];
}

// Single-block exclusive scan of the NB_SCAN block totals (in place).
__global__ void k_scan_totals() {
    __shared__ int sh[128];
    int v = (threadIdx.x < NB_SCAN) ? g_blocktotals[threadIdx.x] : 0;
    sh[threadIdx.x] = v;
    __syncthreads();
    #pragma unroll
    for (int off = 1; off < 128; off <<= 1) {
        int t = (threadIdx.x >= off) ? sh[threadIdx.x - off] : 0;
        __syncthreads();
        sh[threadIdx.x] += t;
        __syncthreads();
    }
    if (threadIdx.x < NB_SCAN) g_blocktotals[threadIdx.x] = sh[threadIdx.x] - v;
}

// Add block offsets: final exclusive ptr; copy into cursors for scatter.
__global__ void k_fixup() {
    int i = blockIdx.x * blockDim.x + threadIdx.x;
    if (i < N_NODES) {
        int p = g_ptr[i] + g_blocktotals[i >> 10];
        g_ptr[i]    = p;
        g_counts[i] = p;   // scatter cursor
    }
    if (i == 0) g_ptr[N_NODES] = N_EDGES;
}

__global__ void k_scatter(const int* __restrict__ rows,
                          const int* __restrict__ cols,
                          const float* __restrict__ vals) {
    int e = blockIdx.x * blockDim.x + threadIdx.x;
    if (e < N_EDGES) {
        int   r = __ldg(rows + e);
        int   c = __ldg(cols + e);
        float v = __ldg(vals + e);
        int pos = atomicAdd(&g_counts[r], 1);
        g_edges[pos] = make_int2(c, __float_as_int(v));
    }
}

// Pull-mode SpMM: 16 threads per row, float4 per thread, register accumulation,
// single coalesced STG.128 per chunk. No atomics on the output.
// Dual-edge unroll: two edge records + two gathers in flight per iteration.
__global__ void k_spmm(const float4* __restrict__ embeds4,
                       float4* __restrict__ out4) {
    int gid = blockIdx.x * blockDim.x + threadIdx.x;
    int r = gid >> 4;
    int c = gid & 15;
    if (r >= N_NODES) return;

    int beg = __ldg(&g_ptr[r]);
    int end = __ldg(&g_ptr[r + 1]);

    float4 acc = make_float4(0.f, 0.f, 0.f, 0.f);
    int i = beg;
    for (; i + 2 <= end; i += 2) {
        int2 cv0 = __ldg(&g_edges[i]);
        int2 cv1 = __ldg(&g_edges[i + 1]);
        float4 x0 = __ldg(embeds4 + (size_t)cv0.x * D4 + c);
        float4 x1 = __ldg(embeds4 + (size_t)cv1.x * D4 + c);
        float v0 = __int_as_float(cv0.y);
        float v1 = __int_as_float(cv1.y);
        acc.x += v0 * x0.x;  acc.y += v0 * x0.y;
        acc.z += v0 * x0.z;  acc.w += v0 * x0.w;
        acc.x += v1 * x1.x;  acc.y += v1 * x1.y;
        acc.z += v1 * x1.z;  acc.w += v1 * x1.w;
    }
    if (i < end) {
        int2 cv = __ldg(&g_edges[i]);
        float  v = __int_as_float(cv.y);
        float4 x = __ldg(embeds4 + (size_t)cv.x * D4 + c);
        acc.x += v * x.x;  acc.y += v * x.y;
        acc.z += v * x.z;  acc.w += v * x.w;
    }
    out4[(size_t)r * D4 + c] = acc;
}

extern "C" void kernel_launch(void* const* d_in, const int* in_sizes, int n_in,
                              void* d_out, int out_size) {
    const int*    rows = (const int*)   d_in[0];
    const int*    cols = (const int*)   d_in[1];
    const float*  vals = (const float*) d_in[2];
    const float4* emb4 = (const float4*)d_in[3];
    float4* out4 = (float4*)d_out;

    k_zero_counts<<<(N_NODES + 255) / 256, 256>>>();
    k_hist<<<(N_EDGES + 255) / 256, 256>>>(rows);
    k_scan_local<<<NB_SCAN, SCAN_T>>>();
    k_scan_totals<<<1, 128>>>();
    k_fixup<<<(N_NODES + 255) / 256, 256>>>();
    k_scatter<<<(N_EDGES + 255) / 256, 256>>>(rows, cols, vals);

    long long total = (long long)N_NODES * 16;
    k_spmm<<<(unsigned)((total + 255) / 256), 256>>>(emb4, out4);
}